// round 7
// baseline (speedup 1.0000x reference)
#include <cuda_runtime.h>
#include <cuda_fp16.h>
#include <cstdint>

// Problem constants (fixed by the reference)
#define T_DIM   8192
#define IN_DIM  4096
#define OUT_DIM 4096
#define RANK    32
#define GS      64
#define G_CNT   64   // IN_DIM / GS

// ---------------------------------------------------------------------------
// Device-global scratch (allocation-free per harness rules)
// ---------------------------------------------------------------------------
__device__ int8_t g_Aq[(size_t)T_DIM * IN_DIM];        // quantized activations (int4 values in s8)
__device__ int8_t g_Bq[(size_t)OUT_DIM * IN_DIM];      // weights packed to s8
__device__ float  g_AscaleT[(size_t)G_CNT * T_DIM];    // per (group, token) act scale, transposed
__device__ __half g_xsf16[(size_t)T_DIM * IN_DIM];     // smoothed acts in fp16 (lora path only)
__device__ __half g_laf16[(size_t)T_DIM * RANK];       // lora_act = xs @ proj_down, fp16
__device__ __half g_puf16[(size_t)OUT_DIM * RANK];     // proj_up fp16
__device__ __half g_pdT[(size_t)RANK * IN_DIM];        // proj_down transposed, fp16

// ---------------------------------------------------------------------------
// K1: smooth + per-(token,group) int4 quantization + fp16 smoothed copy
// One warp per (token, group): 64 elements (2 per lane).
// ---------------------------------------------------------------------------
__global__ void k1_quant(const float* __restrict__ x, const float* __restrict__ smooth) {
    int warp = (blockIdx.x * blockDim.x + threadIdx.x) >> 5;
    int lane = threadIdx.x & 31;
    int t = warp >> 6;        // token
    int g = warp & 63;        // group
    int base = g * GS;
    size_t xoff = (size_t)t * IN_DIM + base;

    float x0 = x[xoff + lane];
    float x1 = x[xoff + lane + 32];
    float s0 = smooth[base + lane];
    float s1 = smooth[base + lane + 32];
    float xs0 = x0 / s0;
    float xs1 = x1 / s1;

    g_xsf16[xoff + lane]      = __float2half(xs0);
    g_xsf16[xoff + lane + 32] = __float2half(xs1);

    float m = fmaxf(fabsf(xs0), fabsf(xs1));
    #pragma unroll
    for (int o = 16; o > 0; o >>= 1)
        m = fmaxf(m, __shfl_xor_sync(0xffffffffu, m, o));

    float ascale = m / 7.0f;                       // matches reference amax/7.0
    if (ascale == 0.0f) ascale = 1.0f;             // matches jnp.where(ascale==0, 1, ascale)

    float q0 = fminf(fmaxf(rintf(xs0 / ascale), -8.0f), 7.0f);  // rint = round-half-even = jnp.round
    float q1 = fminf(fmaxf(rintf(xs1 / ascale), -8.0f), 7.0f);

    g_Aq[xoff + lane]      = (int8_t)q0;
    g_Aq[xoff + lane + 32] = (int8_t)q1;
    if (lane == 0) g_AscaleT[(size_t)g * T_DIM + t] = ascale;
}

// ---------------------------------------------------------------------------
// K2: pack int32 weights -> s8
// ---------------------------------------------------------------------------
__global__ void k2_packw(const int* __restrict__ qw) {
    size_t idx = (size_t)blockIdx.x * blockDim.x + threadIdx.x;   // over OUT*IN/4
    int4 v = ((const int4*)qw)[idx];
    char4 c;
    c.x = (char)v.x; c.y = (char)v.y; c.z = (char)v.z; c.w = (char)v.w;
    ((char4*)g_Bq)[idx] = c;
}

// ---------------------------------------------------------------------------
// K2b: fp32 -> fp16 conversions for the lora operands (+ transpose proj_down)
// idx over OUT*RANK == IN*RANK == 131072
// ---------------------------------------------------------------------------
__global__ void k2_convert(const float* __restrict__ pu, const float* __restrict__ pd) {
    int idx = blockIdx.x * blockDim.x + threadIdx.x;
    g_puf16[idx] = __float2half(pu[idx]);
    int r = idx >> 12;          // 0..31
    int k = idx & 4095;         // 0..4095
    g_pdT[(size_t)r * IN_DIM + k] = __float2half(pd[(size_t)k * RANK + r]);
}

// ---------------------------------------------------------------------------
// K3: lora_act = xs @ proj_down   [T, 4096] x [4096, 32] -> [T, 32]  (fp16 HMMA)
// 64 blocks x 256 threads; warp w handles 16 rows, all 4 n8 tiles.
// Fragments loaded straight from global (L2-cached, tiny kernel).
// ---------------------------------------------------------------------------
__global__ void k3_lora() {
    int warp = threadIdx.x >> 5;
    int lane = threadIdx.x & 31;
    int gid = lane >> 2;        // 0..7
    int tig = lane & 3;         // 0..3
    int m0 = blockIdx.x * 128 + warp * 16;

    float acc[4][4];
    #pragma unroll
    for (int ni = 0; ni < 4; ni++)
        #pragma unroll
        for (int j = 0; j < 4; j++) acc[ni][j] = 0.0f;

    const uint32_t* xsr0 = (const uint32_t*)(g_xsf16 + (size_t)(m0 + gid) * IN_DIM);
    const uint32_t* xsr1 = (const uint32_t*)(g_xsf16 + (size_t)(m0 + gid + 8) * IN_DIM);

    #pragma unroll 4
    for (int ks = 0; ks < IN_DIM / 16; ks++) {
        int kb = ks * 8 + tig;                      // index in units of 2 halves
        uint32_t a0 = xsr0[kb];
        uint32_t a1 = xsr1[kb];
        uint32_t a2 = xsr0[kb + 4];
        uint32_t a3 = xsr1[kb + 4];
        #pragma unroll
        for (int ni = 0; ni < 4; ni++) {
            int c = ni * 8 + gid;
            const uint32_t* bp = (const uint32_t*)(g_pdT + (size_t)c * IN_DIM);
            uint32_t b0 = bp[kb];
            uint32_t b1 = bp[kb + 4];
            asm volatile(
                "mma.sync.aligned.m16n8k16.row.col.f32.f16.f16.f32 "
                "{%0,%1,%2,%3},{%4,%5,%6,%7},{%8,%9},{%0,%1,%2,%3};"
                : "+f"(acc[ni][0]), "+f"(acc[ni][1]), "+f"(acc[ni][2]), "+f"(acc[ni][3])
                : "r"(a0), "r"(a1), "r"(a2), "r"(a3), "r"(b0), "r"(b1));
        }
    }

    #pragma unroll
    for (int ni = 0; ni < 4; ni++) {
        __half2 lo = __floats2half2_rn(acc[ni][0], acc[ni][1]);
        __half2 hi = __floats2half2_rn(acc[ni][2], acc[ni][3]);
        int col = ni * 8 + tig * 2;
        *(__half2*)(g_laf16 + (size_t)(m0 + gid) * RANK + col)     = lo;
        *(__half2*)(g_laf16 + (size_t)(m0 + gid + 8) * RANK + col) = hi;
    }
}

// ---------------------------------------------------------------------------
// K4: main W4A4 GEMM with per-group rescale + fused lora-up.
// Block tile 128x128, 256 threads (2x4 warps of 64x32), K-loop of 64 groups.
// Per group: IMMA m16n8k32.s8 (2 ksteps) exact int32 sums -> fp32 rescale by
// ascale[row,g]*wscale[g,col]. Epilogue: 2 HMMA ksteps add lora (rank 32).
// Shared tiles use 80B row stride: 16B-aligned, conflict-free fragment LDS.
// ---------------------------------------------------------------------------
__global__ void __launch_bounds__(256)
k4_main(const float* __restrict__ wscales, float* __restrict__ out) {
    __shared__ __align__(16) char sA[128 * 80];
    __shared__ __align__(16) char sB[128 * 80];
    __shared__ float sAs[128];
    __shared__ float sWs[128];

    int tid  = threadIdx.x;
    int warp = tid >> 5;
    int lane = tid & 31;
    int gid  = lane >> 2;            // 0..7
    int tig  = lane & 3;             // 0..3
    int wm   = (warp >> 2) * 64;     // warp row offset (0 or 64)
    int wn   = (warp & 3) * 32;      // warp col offset (0..96)

    // L2-friendly block swizzle: 8x32 chunks of blocks
    int bid    = blockIdx.x;
    int chunk  = bid >> 8;                  // 0..7
    int within = bid & 255;
    int mb     = chunk * 8 + (within & 7);  // 0..63
    int nb     = within >> 3;               // 0..31
    int m0 = mb * 128, n0 = nb * 128;

    // staging: each thread owns 32 contiguous bytes of one tile row (2x int4)
    int row = tid >> 1;                 // 0..127
    int qh  = (tid & 1) * 2;            // 16B-chunk pair start: 0 or 2
    const int4* gA = (const int4*)(g_Aq + (size_t)(m0 + row) * IN_DIM) + qh;
    const int4* gB = (const int4*)(g_Bq + (size_t)(n0 + row) * IN_DIM) + qh;
    int4* sAp = (int4*)(sA + row * 80 + qh * 16);
    int4* sBp = (int4*)(sB + row * 80 + qh * 16);

    float acc[4][4][4];
    #pragma unroll
    for (int a = 0; a < 4; a++)
        #pragma unroll
        for (int b = 0; b < 4; b++)
            #pragma unroll
            for (int c = 0; c < 4; c++) acc[a][b][c] = 0.0f;

    int4 rA0, rA1, rB0, rB1;
    float rS = 0.0f;

    // prologue: stage group 0
    rA0 = gA[0]; rA1 = gA[1]; rB0 = gB[0]; rB1 = gB[1];
    if (tid < 128) rS = g_AscaleT[(size_t)0 * T_DIM + m0 + tid];
    else           rS = wscales[(size_t)0 * OUT_DIM + n0 + (tid - 128)];
    sAp[0] = rA0; sAp[1] = rA1; sBp[0] = rB0; sBp[1] = rB1;
    if (tid < 128) sAs[tid] = rS; else sWs[tid - 128] = rS;
    __syncthreads();

    #pragma unroll 1
    for (int g = 0; g < G_CNT; g++) {
        // prefetch next group into registers
        if (g + 1 < G_CNT) {
            const int4* pA = gA + (g + 1) * 4;
            const int4* pB = gB + (g + 1) * 4;
            rA0 = pA[0]; rA1 = pA[1]; rB0 = pB[0]; rB1 = pB[1];
            if (tid < 128) rS = g_AscaleT[(size_t)(g + 1) * T_DIM + m0 + tid];
            else           rS = wscales[(size_t)(g + 1) * OUT_DIM + n0 + (tid - 128)];
        }

        // --- compute current group from shared ---
        uint32_t bf[4][2][2];
        #pragma unroll
        for (int ni = 0; ni < 4; ni++) {
            const char* bptr = sB + (wn + ni * 8 + gid) * 80 + tig * 4;
            #pragma unroll
            for (int ks = 0; ks < 2; ks++) {
                bf[ni][ks][0] = *(const uint32_t*)(bptr + ks * 32);
                bf[ni][ks][1] = *(const uint32_t*)(bptr + ks * 32 + 16);
            }
        }
        float asLo[4], asHi[4];
        #pragma unroll
        for (int mi = 0; mi < 4; mi++) {
            asLo[mi] = sAs[wm + mi * 16 + gid];
            asHi[mi] = sAs[wm + mi * 16 + gid + 8];
        }
        float ws0[4], ws1[4];
        #pragma unroll
        for (int ni = 0; ni < 4; ni++) {
            ws0[ni] = sWs[wn + ni * 8 + tig * 2];
            ws1[ni] = sWs[wn + ni * 8 + tig * 2 + 1];
        }

        #pragma unroll
        for (int mi = 0; mi < 4; mi++) {
            const char* aptr = sA + (wm + mi * 16 + gid) * 80 + tig * 4;
            uint32_t af[2][4];
            #pragma unroll
            for (int ks = 0; ks < 2; ks++) {
                af[ks][0] = *(const uint32_t*)(aptr + ks * 32);
                af[ks][1] = *(const uint32_t*)(aptr + 8 * 80 + ks * 32);
                af[ks][2] = *(const uint32_t*)(aptr + ks * 32 + 16);
                af[ks][3] = *(const uint32_t*)(aptr + 8 * 80 + ks * 32 + 16);
            }
            #pragma unroll
            for (int ni = 0; ni < 4; ni++) {
                int d0 = 0, d1 = 0, d2 = 0, d3 = 0;
                asm volatile(
                    "mma.sync.aligned.m16n8k32.row.col.s32.s8.s8.s32 "
                    "{%0,%1,%2,%3},{%4,%5,%6,%7},{%8,%9},{%0,%1,%2,%3};"
                    : "+r"(d0), "+r"(d1), "+r"(d2), "+r"(d3)
                    : "r"(af[0][0]), "r"(af[0][1]), "r"(af[0][2]), "r"(af[0][3]),
                      "r"(bf[ni][0][0]), "r"(bf[ni][0][1]));
                asm volatile(
                    "mma.sync.aligned.m16n8k32.row.col.s32.s8.s8.s32 "
                    "{%0,%1,%2,%3},{%4,%5,%6,%7},{%8,%9},{%0,%1,%2,%3};"
                    : "+r"(d0), "+r"(d1), "+r"(d2), "+r"(d3)
                    : "r"(af[1][0]), "r"(af[1][1]), "r"(af[1][2]), "r"(af[1][3]),
                      "r"(bf[ni][1][0]), "r"(bf[ni][1][1]));
                // exact int sums -> fp32 rescale-accumulate
                float pLo0 = asLo[mi] * ws0[ni];
                float pLo1 = asLo[mi] * ws1[ni];
                float pHi0 = asHi[mi] * ws0[ni];
                float pHi1 = asHi[mi] * ws1[ni];
                acc[mi][ni][0] = fmaf((float)d0, pLo0, acc[mi][ni][0]);
                acc[mi][ni][1] = fmaf((float)d1, pLo1, acc[mi][ni][1]);
                acc[mi][ni][2] = fmaf((float)d2, pHi0, acc[mi][ni][2]);
                acc[mi][ni][3] = fmaf((float)d3, pHi1, acc[mi][ni][3]);
            }
        }
        __syncthreads();
        if (g + 1 < G_CNT) {
            sAp[0] = rA0; sAp[1] = rA1; sBp[0] = rB0; sBp[1] = rB1;
            if (tid < 128) sAs[tid] = rS; else sWs[tid - 128] = rS;
        }
        __syncthreads();
    }

    // --- epilogue: fused lora (rank 32) via fp16 HMMA into the same accumulators ---
    {
        const int4* gla = (const int4*)(g_laf16 + (size_t)(m0 + row) * RANK) + qh;
        const int4* gpu = (const int4*)(g_puf16 + (size_t)(n0 + row) * RANK) + qh;
        sAp[0] = gla[0]; sAp[1] = gla[1];
        sBp[0] = gpu[0]; sBp[1] = gpu[1];
    }
    __syncthreads();

    uint32_t bl[4][2][2];
    #pragma unroll
    for (int ni = 0; ni < 4; ni++) {
        const char* bptr = sB + (wn + ni * 8 + gid) * 80 + tig * 4;
        #pragma unroll
        for (int ks = 0; ks < 2; ks++) {
            bl[ni][ks][0] = *(const uint32_t*)(bptr + ks * 32);
            bl[ni][ks][1] = *(const uint32_t*)(bptr + ks * 32 + 16);
        }
    }
    #pragma unroll
    for (int mi = 0; mi < 4; mi++) {
        const char* aptr = sA + (wm + mi * 16 + gid) * 80 + tig * 4;
        #pragma unroll
        for (int ks = 0; ks < 2; ks++) {
            uint32_t a0 = *(const uint32_t*)(aptr + ks * 32);
            uint32_t a1 = *(const uint32_t*)(aptr + 8 * 80 + ks * 32);
            uint32_t a2 = *(const uint32_t*)(aptr + ks * 32 + 16);
            uint32_t a3 = *(const uint32_t*)(aptr + 8 * 80 + ks * 32 + 16);
            #pragma unroll
            for (int ni = 0; ni < 4; ni++) {
                asm volatile(
                    "mma.sync.aligned.m16n8k16.row.col.f32.f16.f16.f32 "
                    "{%0,%1,%2,%3},{%4,%5,%6,%7},{%8,%9},{%0,%1,%2,%3};"
                    : "+f"(acc[mi][ni][0]), "+f"(acc[mi][ni][1]),
                      "+f"(acc[mi][ni][2]), "+f"(acc[mi][ni][3])
                    : "r"(a0), "r"(a1), "r"(a2), "r"(a3),
                      "r"(bl[ni][ks][0]), "r"(bl[ni][ks][1]));
            }
        }
    }

    // --- store ---
    #pragma unroll
    for (int mi = 0; mi < 4; mi++) {
        int r0 = m0 + wm + mi * 16 + gid;
        #pragma unroll
        for (int ni = 0; ni < 4; ni++) {
            int c = n0 + wn + ni * 8 + tig * 2;
            *(float2*)(out + (size_t)r0 * OUT_DIM + c) =
                make_float2(acc[mi][ni][0], acc[mi][ni][1]);
            *(float2*)(out + (size_t)(r0 + 8) * OUT_DIM + c) =
                make_float2(acc[mi][ni][2], acc[mi][ni][3]);
        }
    }
}

// ---------------------------------------------------------------------------
// kernel_launch
// inputs: x[f32], qweight[i32], wscales[f32], smooth_factor[f32],
//         proj_down[f32], proj_up[f32]; output: f32 [T, OUT]
// ---------------------------------------------------------------------------
extern "C" void kernel_launch(void* const* d_in, const int* in_sizes, int n_in,
                              void* d_out, int out_size) {
    (void)in_sizes; (void)n_in; (void)out_size;
    const float* x         = (const float*)d_in[0];
    const int*   qweight   = (const int*)d_in[1];
    const float* wscales   = (const float*)d_in[2];
    const float* smooth    = (const float*)d_in[3];
    const float* proj_down = (const float*)d_in[4];
    const float* proj_up   = (const float*)d_in[5];
    float* out = (float*)d_out;

    k1_quant<<<(T_DIM * G_CNT) / 8, 256>>>(x, smooth);
    k2_packw<<<(OUT_DIM / 4) * (IN_DIM / 256), 256>>>(qweight);
    k2_convert<<<(OUT_DIM * RANK) / 256, 256>>>(proj_up, proj_down);
    k3_lora<<<T_DIM / 128, 256>>>();
    k4_main<<<(T_DIM / 128) * (OUT_DIM / 128), 256>>>(wscales, out);
}

// round 8
// speedup vs baseline: 1.0816x; 1.0816x over previous
#include <cuda_runtime.h>
#include <cuda_fp16.h>
#include <cstdint>

// Problem constants (fixed by the reference)
#define T_DIM   8192
#define IN_DIM  4096
#define OUT_DIM 4096
#define RANK    32
#define GS      64
#define G_CNT   64   // IN_DIM / GS

// ---------------------------------------------------------------------------
// Device-global scratch (allocation-free per harness rules)
// ---------------------------------------------------------------------------
__device__ int8_t g_Aq[(size_t)T_DIM * IN_DIM];        // quantized activations (int4 in s8)
__device__ int8_t g_Bq[(size_t)OUT_DIM * IN_DIM];      // weights packed to s8
__device__ float  g_AscaleT[(size_t)G_CNT * T_DIM];    // per (group, token) act scale, transposed
__device__ __half g_xsf16[(size_t)T_DIM * IN_DIM];     // smoothed acts fp16 (lora path)
__device__ float  g_lapart[8][(size_t)T_DIM * RANK];   // split-K lora partials
__device__ __half g_laf16[(size_t)T_DIM * RANK];       // lora_act fp16
__device__ __half g_puf16[(size_t)OUT_DIM * RANK];     // proj_up fp16
__device__ __half g_pdT[(size_t)RANK * IN_DIM];        // proj_down transposed fp16

// ---------------------------------------------------------------------------
// Helpers
// ---------------------------------------------------------------------------
#define CP_ASYNC16(dst, src) \
    asm volatile("cp.async.cg.shared.global [%0], [%1], 16;\n" :: "r"(dst), "l"(src))

__device__ __forceinline__ uint32_t swz(uint32_t base, int row, int chunk) {
    // 64B rows of 4x16B chunks; physical chunk = c ^ ((row>>1)&3)
    return base + (uint32_t)(row * 64 + ((chunk ^ ((row >> 1) & 3)) << 4));
}

__device__ __forceinline__ void ldsm4(uint32_t addr, uint32_t f[4]) {
    asm volatile("ldmatrix.sync.aligned.m8n8.x4.shared.b16 {%0,%1,%2,%3}, [%4];"
                 : "=r"(f[0]), "=r"(f[1]), "=r"(f[2]), "=r"(f[3]) : "r"(addr));
}

// exact int (|d| < 2^22) -> float via bit trick: IADD + FADD, no I2F
__device__ __forceinline__ float i2f_fast(int d) {
    return __int_as_float(d + 0x4B400000) - 12582912.0f;
}

// ---------------------------------------------------------------------------
// K1: smooth + per-(token,group) int4 quantization + fp16 smoothed copy
// ---------------------------------------------------------------------------
__global__ void k1_quant(const float* __restrict__ x, const float* __restrict__ smooth) {
    int warp = (blockIdx.x * blockDim.x + threadIdx.x) >> 5;
    int lane = threadIdx.x & 31;
    int t = warp >> 6;
    int g = warp & 63;
    int base = g * GS;
    size_t xoff = (size_t)t * IN_DIM + base;

    float xs0 = x[xoff + lane] / smooth[base + lane];
    float xs1 = x[xoff + lane + 32] / smooth[base + lane + 32];

    g_xsf16[xoff + lane]      = __float2half(xs0);
    g_xsf16[xoff + lane + 32] = __float2half(xs1);

    float m = fmaxf(fabsf(xs0), fabsf(xs1));
    #pragma unroll
    for (int o = 16; o > 0; o >>= 1)
        m = fmaxf(m, __shfl_xor_sync(0xffffffffu, m, o));

    float ascale = m / 7.0f;
    if (ascale == 0.0f) ascale = 1.0f;

    float q0 = fminf(fmaxf(rintf(xs0 / ascale), -8.0f), 7.0f);
    float q1 = fminf(fmaxf(rintf(xs1 / ascale), -8.0f), 7.0f);

    g_Aq[xoff + lane]      = (int8_t)q0;
    g_Aq[xoff + lane + 32] = (int8_t)q1;
    if (lane == 0) g_AscaleT[(size_t)g * T_DIM + t] = ascale;
}

// ---------------------------------------------------------------------------
// K2: pack int32 weights -> s8
// ---------------------------------------------------------------------------
__global__ void k2_packw(const int* __restrict__ qw) {
    size_t idx = (size_t)blockIdx.x * blockDim.x + threadIdx.x;
    int4 v = ((const int4*)qw)[idx];
    char4 c;
    c.x = (char)v.x; c.y = (char)v.y; c.z = (char)v.z; c.w = (char)v.w;
    ((char4*)g_Bq)[idx] = c;
}

// ---------------------------------------------------------------------------
// K2b: fp16 conversions for lora operands (+ transpose proj_down)
// ---------------------------------------------------------------------------
__global__ void k2_convert(const float* __restrict__ pu, const float* __restrict__ pd) {
    int idx = blockIdx.x * blockDim.x + threadIdx.x;
    g_puf16[idx] = __float2half(pu[idx]);
    int r = idx >> 12;
    int k = idx & 4095;
    g_pdT[(size_t)r * IN_DIM + k] = __float2half(pd[(size_t)k * RANK + r]);
}

// ---------------------------------------------------------------------------
// K3: lora partials, split-K x8.  grid = 64 m-blocks * 8 k-slices.
// ---------------------------------------------------------------------------
__global__ void k3_lora() {
    int warp = threadIdx.x >> 5;
    int lane = threadIdx.x & 31;
    int gid = lane >> 2;
    int tig = lane & 3;
    int mblk   = blockIdx.x >> 3;
    int kslice = blockIdx.x & 7;
    int m0 = mblk * 128 + warp * 16;

    float acc[4][4];
    #pragma unroll
    for (int ni = 0; ni < 4; ni++)
        #pragma unroll
        for (int j = 0; j < 4; j++) acc[ni][j] = 0.0f;

    const uint32_t* xsr0 = (const uint32_t*)(g_xsf16 + (size_t)(m0 + gid) * IN_DIM);
    const uint32_t* xsr1 = (const uint32_t*)(g_xsf16 + (size_t)(m0 + gid + 8) * IN_DIM);

    int ks0 = kslice * 32;
    #pragma unroll 4
    for (int ks = ks0; ks < ks0 + 32; ks++) {
        int kb = ks * 8 + tig;
        uint32_t a0 = xsr0[kb];
        uint32_t a1 = xsr1[kb];
        uint32_t a2 = xsr0[kb + 4];
        uint32_t a3 = xsr1[kb + 4];
        #pragma unroll
        for (int ni = 0; ni < 4; ni++) {
            int c = ni * 8 + gid;
            const uint32_t* bp = (const uint32_t*)(g_pdT + (size_t)c * IN_DIM);
            uint32_t b0 = bp[kb];
            uint32_t b1 = bp[kb + 4];
            asm volatile(
                "mma.sync.aligned.m16n8k16.row.col.f32.f16.f16.f32 "
                "{%0,%1,%2,%3},{%4,%5,%6,%7},{%8,%9},{%0,%1,%2,%3};"
                : "+f"(acc[ni][0]), "+f"(acc[ni][1]), "+f"(acc[ni][2]), "+f"(acc[ni][3])
                : "r"(a0), "r"(a1), "r"(a2), "r"(a3), "r"(b0), "r"(b1));
        }
    }

    float* dst = g_lapart[kslice];
    #pragma unroll
    for (int ni = 0; ni < 4; ni++) {
        int col = ni * 8 + tig * 2;
        *(float2*)(dst + (size_t)(m0 + gid) * RANK + col)     = make_float2(acc[ni][0], acc[ni][1]);
        *(float2*)(dst + (size_t)(m0 + gid + 8) * RANK + col) = make_float2(acc[ni][2], acc[ni][3]);
    }
}

// K3b: reduce 8 partials -> fp16 lora_act
__global__ void k3b_reduce() {
    int idx = blockIdx.x * blockDim.x + threadIdx.x;   // over T*RANK
    float s = 0.0f;
    #pragma unroll
    for (int i = 0; i < 8; i++) s += g_lapart[i][idx];
    g_laf16[idx] = __float2half(s);
}

// ---------------------------------------------------------------------------
// K4: main W4A4 GEMM. 128x128 tile, 256 thr (2x4 warps of 64x32).
// 3-stage cp.async pipeline, K-step = 64B (1 group). ldmatrix fragment loads.
// Exact int32 IMMA per group -> bit-trick float -> fp32 rescale-accumulate.
// Epilogue: rank-32 lora via HMMA into the same accumulators.
// ---------------------------------------------------------------------------
__global__ void __launch_bounds__(256)
k4_main(const float* __restrict__ wscales, float* __restrict__ out) {
    __shared__ __align__(16) char sT[3][16384];   // per stage: A[0:8192), B[8192:16384)
    uint32_t sbase = (uint32_t)__cvta_generic_to_shared(&sT[0][0]);

    int tid  = threadIdx.x;
    int lane = tid & 31;
    int warp = tid >> 5;
    int gid  = lane >> 2;
    int tig  = lane & 3;
    int wm   = (warp >> 2) * 64;
    int wn   = (warp & 3) * 32;

    // L2-friendly block swizzle
    int bid = blockIdx.x;
    int mb  = (bid >> 8) * 8 + (bid & 7);
    int nb  = (bid & 255) >> 3;
    int m0 = mb * 128, n0 = nb * 128;

    // cp.async staging assignment: thread -> (row, 2 chunks)
    int srow = tid >> 1;
    int sc0  = (tid & 1) * 2;
    const int8_t* srcA = g_Aq + (size_t)(m0 + srow) * IN_DIM + sc0 * 16;
    const int8_t* srcB = g_Bq + (size_t)(n0 + srow) * IN_DIM + sc0 * 16;

    // ldmatrix lane-dependent address parts
    int rA_off = ((lane >> 3) & 1) * 8 + (lane & 7);  // A-style: mats {r0-7 cL, r8-15 cL, r0-7 cH, r8-15 cH}
    int cA_off = lane >> 4;
    int rB_off = (lane >> 4) * 8 + (lane & 7);        // B-style: mats {r0-7 cL, r0-7 cH, r8-15 cL, r8-15 cH}
    int cB_off = (lane >> 3) & 1;

    float acc[4][4][4];
    #pragma unroll
    for (int a = 0; a < 4; a++)
        #pragma unroll
        for (int b = 0; b < 4; b++)
            #pragma unroll
            for (int c = 0; c < 4; c++) acc[a][b][c] = 0.0f;

    // prologue: stage groups 0 and 1
    #pragma unroll
    for (int st = 0; st < 2; st++) {
        uint32_t aB = sbase + st * 16384, bB = aB + 8192;
        CP_ASYNC16(swz(aB, srow, sc0),     srcA + st * 64);
        CP_ASYNC16(swz(aB, srow, sc0 + 1), srcA + st * 64 + 16);
        CP_ASYNC16(swz(bB, srow, sc0),     srcB + st * 64);
        CP_ASYNC16(swz(bB, srow, sc0 + 1), srcB + st * 64 + 16);
        asm volatile("cp.async.commit_group;\n" ::);
    }

    #pragma unroll 1
    for (int g = 0; g < G_CNT; g++) {
        asm volatile("cp.async.wait_group 1;\n" ::);
        __syncthreads();

        // prefetch group g+2 (always commit to keep group counting uniform)
        int gp = g + 2;
        if (gp < G_CNT) {
            int st = gp % 3;
            uint32_t aB = sbase + st * 16384, bB = aB + 8192;
            CP_ASYNC16(swz(aB, srow, sc0),     srcA + gp * 64);
            CP_ASYNC16(swz(aB, srow, sc0 + 1), srcA + gp * 64 + 16);
            CP_ASYNC16(swz(bB, srow, sc0),     srcB + gp * 64);
            CP_ASYNC16(swz(bB, srow, sc0 + 1), srcB + gp * 64 + 16);
        }
        asm volatile("cp.async.commit_group;\n" ::);

        int st = g % 3;
        uint32_t aB = sbase + st * 16384, bB = aB + 8192;

        // scales (L2-hot)
        float aLo[4], aHi[4];
        #pragma unroll
        for (int mi = 0; mi < 4; mi++) {
            const float* p = &g_AscaleT[(size_t)g * T_DIM + m0 + wm + mi * 16 + gid];
            aLo[mi] = __ldg(p);
            aHi[mi] = __ldg(p + 8);
        }
        float2 wsv[4];
        #pragma unroll
        for (int ni = 0; ni < 4; ni++)
            wsv[ni] = __ldg((const float2*)&wscales[(size_t)g * OUT_DIM + n0 + wn + ni * 8 + tig * 2]);

        // B fragments: [pair p][k-slice s] -> {b0,b1 of ni=2p ; b0,b1 of ni=2p+1}
        uint32_t bfr[2][2][4];
        #pragma unroll
        for (int p = 0; p < 2; p++)
            #pragma unroll
            for (int s = 0; s < 2; s++)
                ldsm4(swz(bB, wn + p * 16 + rB_off, 2 * s + cB_off), bfr[p][s]);

        #pragma unroll
        for (int mi = 0; mi < 4; mi++) {
            uint32_t afr[2][4];
            #pragma unroll
            for (int s = 0; s < 2; s++)
                ldsm4(swz(aB, wm + mi * 16 + rA_off, 2 * s + cA_off), afr[s]);

            #pragma unroll
            for (int ni = 0; ni < 4; ni++) {
                int p = ni >> 1, q = ni & 1;
                int d0 = 0, d1 = 0, d2 = 0, d3 = 0;
                asm volatile(
                    "mma.sync.aligned.m16n8k32.row.col.s32.s8.s8.s32 "
                    "{%0,%1,%2,%3},{%4,%5,%6,%7},{%8,%9},{%0,%1,%2,%3};"
                    : "+r"(d0), "+r"(d1), "+r"(d2), "+r"(d3)
                    : "r"(afr[0][0]), "r"(afr[0][1]), "r"(afr[0][2]), "r"(afr[0][3]),
                      "r"(bfr[p][0][2 * q]), "r"(bfr[p][0][2 * q + 1]));
                asm volatile(
                    "mma.sync.aligned.m16n8k32.row.col.s32.s8.s8.s32 "
                    "{%0,%1,%2,%3},{%4,%5,%6,%7},{%8,%9},{%0,%1,%2,%3};"
                    : "+r"(d0), "+r"(d1), "+r"(d2), "+r"(d3)
                    : "r"(afr[1][0]), "r"(afr[1][1]), "r"(afr[1][2]), "r"(afr[1][3]),
                      "r"(bfr[p][1][2 * q]), "r"(bfr[p][1][2 * q + 1]));

                float w0 = wsv[ni].x, w1 = wsv[ni].y;
                float p00 = aLo[mi] * w0, p01 = aLo[mi] * w1;
                float p10 = aHi[mi] * w0, p11 = aHi[mi] * w1;
                acc[mi][ni][0] = fmaf(i2f_fast(d0), p00, acc[mi][ni][0]);
                acc[mi][ni][1] = fmaf(i2f_fast(d1), p01, acc[mi][ni][1]);
                acc[mi][ni][2] = fmaf(i2f_fast(d2), p10, acc[mi][ni][2]);
                acc[mi][ni][3] = fmaf(i2f_fast(d3), p11, acc[mi][ni][3]);
            }
        }
    }

    // ---------------- epilogue: fused lora (rank 32) ----------------
    __syncthreads();
    {
        // stage lora_act (fp16, 64B rows) into stage-0 A region; proj_up into B region
        int4 va0 = ((const int4*)g_laf16)[(size_t)(m0 + srow) * 4 + sc0];
        int4 va1 = ((const int4*)g_laf16)[(size_t)(m0 + srow) * 4 + sc0 + 1];
        int4 vb0 = ((const int4*)g_puf16)[(size_t)(n0 + srow) * 4 + sc0];
        int4 vb1 = ((const int4*)g_puf16)[(size_t)(n0 + srow) * 4 + sc0 + 1];
        int sw = (srow >> 1) & 3;
        *(int4*)(&sT[0][0] + srow * 64 + ((sc0 ^ sw) << 4))           = va0;
        *(int4*)(&sT[0][0] + srow * 64 + (((sc0 + 1) ^ sw) << 4))     = va1;
        *(int4*)(&sT[0][8192] + srow * 64 + ((sc0 ^ sw) << 4))        = vb0;
        *(int4*)(&sT[0][8192] + srow * 64 + (((sc0 + 1) ^ sw) << 4))  = vb1;
    }
    __syncthreads();
    {
        uint32_t aB = sbase, bB = sbase + 8192;
        uint32_t bh[2][2][4];
        #pragma unroll
        for (int p = 0; p < 2; p++)
            #pragma unroll
            for (int s = 0; s < 2; s++)
                ldsm4(swz(bB, wn + p * 16 + rB_off, 2 * s + cB_off), bh[p][s]);

        #pragma unroll
        for (int mi = 0; mi < 4; mi++) {
            uint32_t ah[2][4];
            #pragma unroll
            for (int s = 0; s < 2; s++)
                ldsm4(swz(aB, wm + mi * 16 + rA_off, 2 * s + cA_off), ah[s]);
            #pragma unroll
            for (int ni = 0; ni < 4; ni++) {
                int p = ni >> 1, q = ni & 1;
                #pragma unroll
                for (int s = 0; s < 2; s++) {
                    asm volatile(
                        "mma.sync.aligned.m16n8k16.row.col.f32.f16.f16.f32 "
                        "{%0,%1,%2,%3},{%4,%5,%6,%7},{%8,%9},{%0,%1,%2,%3};"
                        : "+f"(acc[mi][ni][0]), "+f"(acc[mi][ni][1]),
                          "+f"(acc[mi][ni][2]), "+f"(acc[mi][ni][3])
                        : "r"(ah[s][0]), "r"(ah[s][1]), "r"(ah[s][2]), "r"(ah[s][3]),
                          "r"(bh[p][s][2 * q]), "r"(bh[p][s][2 * q + 1]));
                }
            }
        }
    }

    // ---------------- store ----------------
    #pragma unroll
    for (int mi = 0; mi < 4; mi++) {
        int r0 = m0 + wm + mi * 16 + gid;
        #pragma unroll
        for (int ni = 0; ni < 4; ni++) {
            int c = n0 + wn + ni * 8 + tig * 2;
            *(float2*)(out + (size_t)r0 * OUT_DIM + c) =
                make_float2(acc[mi][ni][0], acc[mi][ni][1]);
            *(float2*)(out + (size_t)(r0 + 8) * OUT_DIM + c) =
                make_float2(acc[mi][ni][2], acc[mi][ni][3]);
        }
    }
}

// ---------------------------------------------------------------------------
// kernel_launch
// ---------------------------------------------------------------------------
extern "C" void kernel_launch(void* const* d_in, const int* in_sizes, int n_in,
                              void* d_out, int out_size) {
    (void)in_sizes; (void)n_in; (void)out_size;
    const float* x         = (const float*)d_in[0];
    const int*   qweight   = (const int*)d_in[1];
    const float* wscales   = (const float*)d_in[2];
    const float* smooth    = (const float*)d_in[3];
    const float* proj_down = (const float*)d_in[4];
    const float* proj_up   = (const float*)d_in[5];
    float* out = (float*)d_out;

    k1_quant<<<(T_DIM * G_CNT) / 8, 256>>>(x, smooth);
    k2_packw<<<(OUT_DIM / 4) * (IN_DIM / 256), 256>>>(qweight);
    k2_convert<<<(OUT_DIM * RANK) / 256, 256>>>(proj_up, proj_down);
    k3_lora<<<(T_DIM / 128) * 8, 256>>>();
    k3b_reduce<<<(T_DIM * RANK) / 256, 256>>>();
    k4_main<<<(T_DIM / 128) * (OUT_DIM / 128), 256>>>(wscales, out);
}

// round 10
// speedup vs baseline: 3.3578x; 3.1043x over previous
#include <cuda_runtime.h>
#include <cuda_fp16.h>
#include <cstdint>

// Problem constants (fixed by the reference)
#define T_DIM   8192
#define IN_DIM  4096
#define OUT_DIM 4096
#define RANK    32
#define GS      64
#define G_CNT   64
#define NCHUNK  65            // 64 main K-chunks + 1 lora chunk (32 lora + 32 zero)
#define TILE_M  128
#define TILE_N  256
#define MT_CNT  (T_DIM / TILE_M)    // 64
#define NT_CNT  (OUT_DIM / TILE_N)  // 16
#define A_CHUNK_H 8192        // 128 rows * 64 halves
#define B_CHUNK_H 16384       // 256 cols * 64 halves
#define A_CHUNK_BYTES 16384
#define B_CHUNK_BYTES 32768
#define STAGE_BYTES 49152
#define NSTAGE  4
#define DSMEM_BYTES (NSTAGE * STAGE_BYTES)   // 192 KB

// ---------------------------------------------------------------------------
// Device-global scratch (allocation-free per harness rules)
// Packed, pre-swizzled operand layouts:
//   g_Apk[mt][chunk][row 0..127][64 halves, 16B-chunk XOR-swizzled by row&7]
//   g_Bpk[nt][chunk][col 0..255][64 halves, swizzled by col&7]
// ---------------------------------------------------------------------------
__device__ __align__(128) __half g_Apk[(size_t)MT_CNT * NCHUNK * A_CHUNK_H];
__device__ __align__(128) __half g_Bpk[(size_t)NT_CNT * NCHUNK * B_CHUNK_H];
__device__ __align__(128) __half g_xsf16[(size_t)T_DIM * IN_DIM];   // smoothed acts (lora)
__device__ __align__(128) float  g_lapart[8][(size_t)T_DIM * RANK]; // split-K lora partials
__device__ __align__(128) __half g_pdT[(size_t)RANK * IN_DIM];      // proj_down^T fp16

// ---------------------------------------------------------------------------
// Helpers (sm_90-level features only: mbarrier + cp.async.bulk + mma.sync)
// ---------------------------------------------------------------------------
__device__ __forceinline__ uint32_t smem_to_u32(const void* p) {
    uint32_t a;
    asm("{ .reg .u64 t; cvta.to.shared.u64 t, %1; cvt.u32.u64 %0, t; }"
        : "=r"(a) : "l"(p));
    return a;
}

__device__ __forceinline__ uint32_t elect_one_pred() {
    uint32_t pred;
    asm volatile(
        "{\n\t.reg .pred p;\n\telect.sync _|p, 0xFFFFFFFF;\n\t"
        "selp.b32 %0, 1, 0, p;\n\t}"
        : "=r"(pred));
    return pred;
}

#define MBARRIER_INIT(mbar, count) \
    asm volatile("mbarrier.init.shared.b64 [%0], %1;" \
        :: "r"((uint32_t)(mbar)), "r"((uint32_t)(count)) : "memory")

#define MBARRIER_INVAL(mbar) \
    asm volatile("mbarrier.inval.shared.b64 [%0];" \
        :: "r"((uint32_t)(mbar)) : "memory")

#define MBARRIER_EXPECT_TX(mbar, bytes) \
    asm volatile("mbarrier.arrive.expect_tx.shared.b64 _, [%0], %1;" \
        :: "r"((uint32_t)(mbar)), "r"((uint32_t)(bytes)) : "memory")

#define MBARRIER_WAIT_PARITY(mbar, parity) do { \
    uint32_t _mbar = (uint32_t)(mbar); \
    uint32_t _par  = (uint32_t)(parity); \
    uint32_t _done; \
    asm volatile( \
        "{\n\t.reg .pred p;\n\t" \
        "mbarrier.try_wait.parity.acquire.cta.shared::cta.b64 p, [%1], %2;\n\t" \
        "selp.b32 %0, 1, 0, p;\n\t}" \
        : "=r"(_done) : "r"(_mbar), "r"(_par) : "memory"); \
    if (!_done) { \
        asm volatile( \
            "{\n\t.reg .pred P1;\n\t" \
            "WAIT_LOOP_%=:\n\t" \
            "mbarrier.try_wait.parity.acquire.cta.shared::cta.b64 P1, [%0], %1, 0x989680;\n\t" \
            "@P1 bra.uni WAIT_DONE_%=;\n\t" \
            "bra.uni WAIT_LOOP_%=;\n\t" \
            "WAIT_DONE_%=:\n\t}" \
            :: "r"(_mbar), "r"(_par) : "memory"); \
    } \
} while (0)

#define FENCE_PROXY_ASYNC() \
    asm volatile("fence.proxy.async.shared::cta;" ::: "memory")

// 1-D bulk copy GMEM -> SMEM with mbarrier transaction completion (SASS: UBLKCP)
#define CP_ASYNC_BULK(dst_smem, src_gmem, bytes, mbar) \
    asm volatile( \
        "cp.async.bulk.shared::cluster.global.mbarrier::complete_tx::bytes " \
        "[%0], [%1], %2, [%3];" \
        :: "r"((uint32_t)(dst_smem)), "l"(src_gmem), "r"((uint32_t)(bytes)), \
           "r"((uint32_t)(mbar)) : "memory")

__device__ __forceinline__ void ldsm4(uint32_t addr, uint32_t f[4]) {
    asm volatile("ldmatrix.sync.aligned.m8n8.x4.shared.b16 {%0,%1,%2,%3}, [%4];"
                 : "=r"(f[0]), "=r"(f[1]), "=r"(f[2]), "=r"(f[3]) : "r"(addr));
}

// swizzled half-index within a 64-half (128B) row: 16B chunk c XORed with (r&7)
__device__ __forceinline__ int swz_h(int h, int r) {
    return (((h >> 3) ^ (r & 7)) << 3) | (h & 7);
}

// ---------------------------------------------------------------------------
// K1: smooth + per-(token,group) int4 quantization; writes xdq fp16 directly
//     into the packed+swizzled A layout, plus smoothed fp16 acts for lora.
// One warp per (token, group).
// ---------------------------------------------------------------------------
__global__ void k1_quant(const float* __restrict__ x, const float* __restrict__ smooth) {
    int warp = (blockIdx.x * blockDim.x + threadIdx.x) >> 5;
    int lane = threadIdx.x & 31;
    int t = warp >> 6;
    int g = warp & 63;
    int base = g * GS;
    size_t xoff = (size_t)t * IN_DIM + base;

    float xs0 = x[xoff + lane] / smooth[base + lane];
    float xs1 = x[xoff + lane + 32] / smooth[base + lane + 32];

    g_xsf16[xoff + lane]      = __float2half(xs0);
    g_xsf16[xoff + lane + 32] = __float2half(xs1);

    float m = fmaxf(fabsf(xs0), fabsf(xs1));
    #pragma unroll
    for (int o = 16; o > 0; o >>= 1)
        m = fmaxf(m, __shfl_xor_sync(0xffffffffu, m, o));

    float ascale = m / 7.0f;                 // matches reference amax/7.0
    if (ascale == 0.0f) ascale = 1.0f;       // matches jnp.where

    float q0 = fminf(fmaxf(rintf(xs0 / ascale), -8.0f), 7.0f);
    float q1 = fminf(fmaxf(rintf(xs1 / ascale), -8.0f), 7.0f);

    int mt = t >> 7, r = t & 127;
    size_t pkbase = ((size_t)(mt * NCHUNK + g) * 128 + r) * 64;
    g_Apk[pkbase + swz_h(lane, r)]      = __float2half(q0 * ascale);
    g_Apk[pkbase + swz_h(lane + 32, r)] = __float2half(q1 * ascale);
}

// ---------------------------------------------------------------------------
// K2: dequantize weights into packed+swizzled B: wdq = qw * wscale[g][o]
// One thread per 16B output chunk (8 halves).  idx over OUT*512.
// ---------------------------------------------------------------------------
__global__ void k2_wdq(const int* __restrict__ qw, const float* __restrict__ wscales) {
    int idx = blockIdx.x * blockDim.x + threadIdx.x;
    int o   = idx >> 9;          // output channel
    int rem = idx & 511;
    int c   = rem >> 3;          // group / chunk
    int c16 = rem & 7;           // 16B chunk within row
    float ws = __ldg(&wscales[(size_t)c * OUT_DIM + o]);

    int k = c * 64 + c16 * 8;
    const int4* qp = (const int4*)(qw + (size_t)o * IN_DIM + k);
    int4 v0 = qp[0], v1 = qp[1];
    __half2 p0 = __floats2half2_rn((float)v0.x * ws, (float)v0.y * ws);
    __half2 p1 = __floats2half2_rn((float)v0.z * ws, (float)v0.w * ws);
    __half2 p2 = __floats2half2_rn((float)v1.x * ws, (float)v1.y * ws);
    __half2 p3 = __floats2half2_rn((float)v1.z * ws, (float)v1.w * ws);
    uint4 w;
    w.x = *(uint32_t*)&p0; w.y = *(uint32_t*)&p1;
    w.z = *(uint32_t*)&p2; w.w = *(uint32_t*)&p3;

    int nt = o >> 8, col = o & 255;
    size_t base = ((size_t)(nt * NCHUNK + c) * 256 + col) * 64;
    int phys16 = c16 ^ (col & 7);
    *(uint4*)(g_Bpk + base + phys16 * 8) = w;
}

// ---------------------------------------------------------------------------
// K2b: proj_down^T fp16; B lora chunk (proj_up fp16 + zero pad).
// idx over IN*RANK = 131072; first 32768 also write one 16B B-tail chunk.
// ---------------------------------------------------------------------------
__global__ void k2_convert(const float* __restrict__ pu, const float* __restrict__ pd) {
    int idx = blockIdx.x * blockDim.x + threadIdx.x;
    int rr = idx >> 12;
    int k  = idx & 4095;
    g_pdT[(size_t)rr * IN_DIM + k] = __float2half(pd[(size_t)k * RANK + rr]);

    if (idx < OUT_DIM * 8) {
        int o = idx >> 3, c16 = idx & 7;
        uint4 w;
        if (c16 < 4) {
            const float* src = pu + (size_t)o * RANK + c16 * 8;
            __half2 p0 = __floats2half2_rn(src[0], src[1]);
            __half2 p1 = __floats2half2_rn(src[2], src[3]);
            __half2 p2 = __floats2half2_rn(src[4], src[5]);
            __half2 p3 = __floats2half2_rn(src[6], src[7]);
            w.x = *(uint32_t*)&p0; w.y = *(uint32_t*)&p1;
            w.z = *(uint32_t*)&p2; w.w = *(uint32_t*)&p3;
        } else {
            w = make_uint4(0, 0, 0, 0);
        }
        int nt = o >> 8, col = o & 255;
        size_t base = ((size_t)(nt * NCHUNK + 64) * 256 + col) * 64;
        int phys16 = c16 ^ (col & 7);
        *(uint4*)(g_Bpk + base + phys16 * 8) = w;
    }
}

// ---------------------------------------------------------------------------
// K3: lora partials, split-K x8 (proven in rounds 8/9).
// ---------------------------------------------------------------------------
__global__ void k3_lora() {
    int warp = threadIdx.x >> 5;
    int lane = threadIdx.x & 31;
    int gid = lane >> 2;
    int tig = lane & 3;
    int mblk   = blockIdx.x >> 3;
    int kslice = blockIdx.x & 7;
    int m0 = mblk * 128 + warp * 16;

    float acc[4][4];
    #pragma unroll
    for (int ni = 0; ni < 4; ni++)
        #pragma unroll
        for (int j = 0; j < 4; j++) acc[ni][j] = 0.0f;

    const uint32_t* xsr0 = (const uint32_t*)(g_xsf16 + (size_t)(m0 + gid) * IN_DIM);
    const uint32_t* xsr1 = (const uint32_t*)(g_xsf16 + (size_t)(m0 + gid + 8) * IN_DIM);

    int ks0 = kslice * 32;
    #pragma unroll 4
    for (int ks = ks0; ks < ks0 + 32; ks++) {
        int kb = ks * 8 + tig;
        uint32_t a0 = xsr0[kb];
        uint32_t a1 = xsr1[kb];
        uint32_t a2 = xsr0[kb + 4];
        uint32_t a3 = xsr1[kb + 4];
        #pragma unroll
        for (int ni = 0; ni < 4; ni++) {
            int c = ni * 8 + gid;
            const uint32_t* bp = (const uint32_t*)(g_pdT + (size_t)c * IN_DIM);
            uint32_t b0 = bp[kb];
            uint32_t b1 = bp[kb + 4];
            asm volatile(
                "mma.sync.aligned.m16n8k16.row.col.f32.f16.f16.f32 "
                "{%0,%1,%2,%3},{%4,%5,%6,%7},{%8,%9},{%0,%1,%2,%3};"
                : "+f"(acc[ni][0]), "+f"(acc[ni][1]), "+f"(acc[ni][2]), "+f"(acc[ni][3])
                : "r"(a0), "r"(a1), "r"(a2), "r"(a3), "r"(b0), "r"(b1));
        }
    }

    float* dst = g_lapart[kslice];
    #pragma unroll
    for (int ni = 0; ni < 4; ni++) {
        int col = ni * 8 + tig * 2;
        *(float2*)(dst + (size_t)(m0 + gid) * RANK + col)     = make_float2(acc[ni][0], acc[ni][1]);
        *(float2*)(dst + (size_t)(m0 + gid + 8) * RANK + col) = make_float2(acc[ni][2], acc[ni][3]);
    }
}

// K3b: reduce partials -> A lora chunk (fp16) + zero pad
__global__ void k3b_reduce() {
    int idx = blockIdx.x * blockDim.x + threadIdx.x;   // over T*RANK
    float s = 0.0f;
    #pragma unroll
    for (int i = 0; i < 8; i++) s += g_lapart[i][idx];
    int t = idx >> 5, rk = idx & 31;
    int mt = t >> 7, r = t & 127;
    size_t base = ((size_t)(mt * NCHUNK + 64) * 128 + r) * 64;
    g_Apk[base + swz_h(rk, r)]      = __float2half(s);
    g_Apk[base + swz_h(rk + 32, r)] = __float2half(0.0f);
}

// ---------------------------------------------------------------------------
// K4: fp16 HMMA GEMM, tile 128x256, 65 K-chunks of 64 halves.
// 4-stage cp.async.bulk pipeline (2 bulk copies per stage), mbarrier full
// barriers + __syncthreads consumption; ldmatrix + mma.sync.m16n8k16 compute.
// ---------------------------------------------------------------------------
__global__ void __launch_bounds__(256, 1)
k4_main(float* __restrict__ out) {
    extern __shared__ __align__(128) char dsm[];
    __shared__ __align__(8) unsigned long long s_full[NSTAGE];

    int tid  = threadIdx.x;
    int wid  = tid >> 5;
    int lane = tid & 31;
    int gid  = lane >> 2;
    int tig  = lane & 3;
    int wm   = (wid >> 2) * 64;     // warp row offset: 0 or 64
    int wn   = (wid & 3) * 64;      // warp col offset: 0,64,128,192

    uint32_t smem = smem_to_u32(dsm);
    uint32_t mb[NSTAGE];
    #pragma unroll
    for (int s = 0; s < NSTAGE; s++) mb[s] = smem_to_u32(&s_full[s]);

    // block swizzle: 16-mt chunks sweep all 16 nt (whole B = 34MB stays in L2)
    int bid = blockIdx.x;
    int mt  = ((bid >> 8) << 4) + (bid & 15);
    int nt  = (bid >> 4) & 15;
    int m0 = mt * TILE_M, n0 = nt * TILE_N;

    const __half* gA = g_Apk + (size_t)mt * NCHUNK * A_CHUNK_H;
    const __half* gB = g_Bpk + (size_t)nt * NCHUNK * B_CHUNK_H;

    if (tid == 0) {
        #pragma unroll
        for (int s = 0; s < NSTAGE; s++) MBARRIER_INIT(mb[s], 1);
    }
    __syncthreads();

    // prologue: fill all 4 stages (chunks 0..3)
    if (wid == 0 && elect_one_pred()) {
        #pragma unroll
        for (int s = 0; s < NSTAGE; s++) {
            uint32_t sA = smem + s * STAGE_BYTES;
            MBARRIER_EXPECT_TX(mb[s], STAGE_BYTES);
            CP_ASYNC_BULK(sA,         gA + (size_t)s * A_CHUNK_H, A_CHUNK_BYTES, mb[s]);
            CP_ASYNC_BULK(sA + A_CHUNK_BYTES, gB + (size_t)s * B_CHUNK_H, B_CHUNK_BYTES, mb[s]);
        }
    }

    // ldmatrix lane-dependent address parts (validated round-8 pattern)
    int rA_off = ((lane >> 3) & 1) * 8 + (lane & 7);
    int cA_off = lane >> 4;           // 0/1
    int rB_off = (lane >> 4) * 8 + (lane & 7);
    int cB_off = (lane >> 3) & 1;     // 0/1

    uint32_t aRow[4], aXor[4], bRow[4], bXor[4];
    #pragma unroll
    for (int mi = 0; mi < 4; mi++) {
        int r = wm + mi * 16 + rA_off;
        aRow[mi] = (uint32_t)(r * 128);
        aXor[mi] = (uint32_t)((r & 7) << 4);
    }
    #pragma unroll
    for (int nb = 0; nb < 4; nb++) {
        int c = wn + nb * 16 + rB_off;
        bRow[nb] = (uint32_t)(c * 128);
        bXor[nb] = (uint32_t)((c & 7) << 4);
    }

    float acc[4][8][4];
    #pragma unroll
    for (int a = 0; a < 4; a++)
        #pragma unroll
        for (int b = 0; b < 8; b++)
            #pragma unroll
            for (int c = 0; c < 4; c++) acc[a][b][c] = 0.0f;

    #pragma unroll 1
    for (int g = 0; g < NCHUNK; g++) {
        int s = g & 3;
        uint32_t sA = smem + s * STAGE_BYTES;
        uint32_t sB = sA + A_CHUNK_BYTES;

        MBARRIER_WAIT_PARITY(mb[s], (g >> 2) & 1);

        #pragma unroll
        for (int ks = 0; ks < 4; ks++) {
            uint32_t cA16 = (uint32_t)((2 * ks + cA_off) << 4);
            uint32_t cB16 = (uint32_t)((2 * ks + cB_off) << 4);

            uint32_t bfr[4][4];
            #pragma unroll
            for (int nb = 0; nb < 4; nb++)
                ldsm4(sB + bRow[nb] + (cB16 ^ bXor[nb]), bfr[nb]);

            #pragma unroll
            for (int mi = 0; mi < 4; mi++) {
                uint32_t afr[4];
                ldsm4(sA + aRow[mi] + (cA16 ^ aXor[mi]), afr);
                #pragma unroll
                for (int nb = 0; nb < 4; nb++) {
                    #pragma unroll
                    for (int q = 0; q < 2; q++) {
                        int ni = nb * 2 + q;
                        asm volatile(
                            "mma.sync.aligned.m16n8k16.row.col.f32.f16.f16.f32 "
                            "{%0,%1,%2,%3},{%4,%5,%6,%7},{%8,%9},{%0,%1,%2,%3};"
                            : "+f"(acc[mi][ni][0]), "+f"(acc[mi][ni][1]),
                              "+f"(acc[mi][ni][2]), "+f"(acc[mi][ni][3])
                            : "r"(afr[0]), "r"(afr[1]), "r"(afr[2]), "r"(afr[3]),
                              "r"(bfr[nb][2 * q]), "r"(bfr[nb][2 * q + 1]));
                    }
                }
            }
        }

        __syncthreads();   // whole CTA done with stage s -> safe to refill

        int gp = g + NSTAGE;
        if (gp < NCHUNK && wid == 0) {
            if (elect_one_pred()) {
                FENCE_PROXY_ASYNC();
                MBARRIER_EXPECT_TX(mb[s], STAGE_BYTES);
                CP_ASYNC_BULK(sA, gA + (size_t)gp * A_CHUNK_H, A_CHUNK_BYTES, mb[s]);
                CP_ASYNC_BULK(sB, gB + (size_t)gp * B_CHUNK_H, B_CHUNK_BYTES, mb[s]);
            }
        }
    }

    // ---------------- store ----------------
    #pragma unroll
    for (int mi = 0; mi < 4; mi++) {
        int r0 = m0 + wm + mi * 16 + gid;
        #pragma unroll
        for (int nb = 0; nb < 4; nb++) {
            #pragma unroll
            for (int q = 0; q < 2; q++) {
                int ni = nb * 2 + q;
                int c = n0 + wn + nb * 16 + q * 8 + tig * 2;
                *(float2*)(out + (size_t)r0 * OUT_DIM + c) =
                    make_float2(acc[mi][ni][0], acc[mi][ni][1]);
                *(float2*)(out + (size_t)(r0 + 8) * OUT_DIM + c) =
                    make_float2(acc[mi][ni][2], acc[mi][ni][3]);
            }
        }
    }

    __syncthreads();
    if (tid == 0) {
        #pragma unroll
        for (int s = 0; s < NSTAGE; s++) MBARRIER_INVAL(mb[s]);
    }
}

// ---------------------------------------------------------------------------
// kernel_launch
// inputs: x[f32], qweight[i32], wscales[f32], smooth_factor[f32],
//         proj_down[f32], proj_up[f32]; output: f32 [T, OUT]
// ---------------------------------------------------------------------------
extern "C" void kernel_launch(void* const* d_in, const int* in_sizes, int n_in,
                              void* d_out, int out_size) {
    (void)in_sizes; (void)n_in; (void)out_size;
    const float* x         = (const float*)d_in[0];
    const int*   qweight   = (const int*)d_in[1];
    const float* wscales   = (const float*)d_in[2];
    const float* smooth    = (const float*)d_in[3];
    const float* proj_down = (const float*)d_in[4];
    const float* proj_up   = (const float*)d_in[5];
    float* out = (float*)d_out;

    cudaFuncSetAttribute(k4_main, cudaFuncAttributeMaxDynamicSharedMemorySize,
                         DSMEM_BYTES);

    k1_quant<<<(T_DIM * G_CNT) / 8, 256>>>(x, smooth);
    k2_wdq<<<(OUT_DIM * 512) / 256, 256>>>(qweight, wscales);
    k2_convert<<<(IN_DIM * RANK) / 256, 256>>>(proj_up, proj_down);
    k3_lora<<<(T_DIM / 128) * 8, 256>>>();
    k3b_reduce<<<(T_DIM * RANK) / 256, 256>>>();
    k4_main<<<MT_CNT * NT_CNT, 256, DSMEM_BYTES>>>(out);
}